// round 2
// baseline (speedup 1.0000x reference)
#include <cuda_runtime.h>
#include <cuda_bf16.h>

// HashNGramEmbedder: out[b,s,:] = ( main_w[tok[b,s]]
//                                   + sum_{n=3..8} ( shared_w[idx_n(b,s)] + size_w[n-3] ) ) / 7
// idx_n(b,s) = ( sum_{j=0}^{n-1} tok[b,s-j] * 260^j  mod 2^23 ) mod 500000,  or 0 if s < n-1.
//
// Shapes (metadata order):
//   d_in[0] tokens   int32  [4, 8192]
//   d_in[1] main_w   f32    [259, 512]
//   d_in[2] shared_w f32    [500000, 512]
//   d_in[3] size_w   f32    [6, 512]
//   d_out            f32    [4, 8192, 512]

#define EMBED_D     512
#define DV          (EMBED_D / 4)      // 128 float4 per row
#define SEQ_LEN     8192
#define N_BATCH     4
#define N_POS       (N_BATCH * SEQ_LEN)
#define HASH_MASK   ((1u << 23) - 1u)
#define N_BUCKETS   500000
#define HASH_BASE   260u
#define INV_CONTRIB (1.0f / 7.0f)

__global__ __launch_bounds__(DV, 8)
void hashngram_embed_kernel(const int*    __restrict__ tokens,
                            const float4* __restrict__ main_w,
                            const float4* __restrict__ shared_w,
                            const float4* __restrict__ size_w,
                            float4*       __restrict__ out)
{
    const int pos = blockIdx.x;            // b * SEQ_LEN + s
    const int s   = pos & (SEQ_LEN - 1);
    const int* t  = tokens + (pos - s);    // row base = b * SEQ_LEN

    // Lanes 0..5 compute the bucket index for n = lane+3 in parallel.
    __shared__ int sh_idx[6];
    if (threadIdx.x < 6) {
        const int n = (int)threadIdx.x + 3;
        int idx = 0;
        if (s >= n - 1) {
            unsigned acc = 0u, pw = 1u;
            #pragma unroll
            for (int j = 0; j < 8; j++) {
                if (j < n)
                    acc = (acc + (unsigned)t[s - j] * pw) & HASH_MASK;
                pw = (pw * HASH_BASE) & HASH_MASK;
            }
            idx = (int)(acc % N_BUCKETS);
        }
        sh_idx[threadIdx.x] = idx;
    }
    __syncthreads();

    const int d   = (int)threadIdx.x;      // float4 lane within the 512-wide row
    const int tok = t[s];                  // broadcast L2 hit

    // Issue all 7 big-row gathers back-to-back (independent -> MLP ~7).
    float4 m  = __ldg(&main_w[(size_t)tok * DV + d]);
    float4 g[6];
    #pragma unroll
    for (int n = 0; n < 6; n++)
        g[n] = __ldg(&shared_w[(size_t)sh_idx[n] * DV + d]);

    // size_w is 12 KB -> L1/L2 resident.
    float4 z[6];
    #pragma unroll
    for (int n = 0; n < 6; n++)
        z[n] = __ldg(&size_w[n * DV + d]);

    float4 acc = m;
    #pragma unroll
    for (int n = 0; n < 6; n++) {
        acc.x += g[n].x + z[n].x;
        acc.y += g[n].y + z[n].y;
        acc.z += g[n].z + z[n].z;
        acc.w += g[n].w + z[n].w;
    }
    acc.x *= INV_CONTRIB;
    acc.y *= INV_CONTRIB;
    acc.z *= INV_CONTRIB;
    acc.w *= INV_CONTRIB;

    // Streaming store: keep the 64 MB output from evicting shared_w lines in L2.
    __stcs(&out[(size_t)pos * DV + d], acc);
}

extern "C" void kernel_launch(void* const* d_in, const int* in_sizes, int n_in,
                              void* d_out, int out_size)
{
    const int*    tokens   = (const int*)d_in[0];
    const float4* main_w   = (const float4*)d_in[1];
    const float4* shared_w = (const float4*)d_in[2];
    const float4* size_w   = (const float4*)d_in[3];
    float4*       out      = (float4*)d_out;

    hashngram_embed_kernel<<<N_POS, DV>>>(tokens, main_w, shared_w, size_w, out);
}

// round 4
// speedup vs baseline: 1.0154x; 1.0154x over previous
#include <cuda_runtime.h>
#include <cuda_bf16.h>

// HashNGramEmbedder, two-phase:
//   K1: per-position rolling-hash index precompute -> g_idx[pos][8] (padded)
//   K0: size_sum7[d] = sum_n size_w[n][d] / 7
//   K2: gather: out[pos] = (main_w[tok] + sum_n shared_w[idx_n]) / 7 + size_sum7
//
// Shapes (metadata order):
//   d_in[0] tokens   int32  [4, 8192]
//   d_in[1] main_w   f32    [259, 512]
//   d_in[2] shared_w f32    [500000, 512]
//   d_in[3] size_w   f32    [6, 512]
//   d_out            f32    [4, 8192, 512]

#define EMBED_D     512
#define DV          (EMBED_D / 4)      // 128 float4 per row
#define SEQ_LEN     8192
#define N_BATCH     4
#define N_POS       (N_BATCH * SEQ_LEN)
#define HASH_MASK   ((1u << 23) - 1u)
#define N_BUCKETS   500000
#define HASH_BASE   260u
#define INV_CONTRIB (1.0f / 7.0f)

// Scratch (allocation-free, __device__ globals per harness rules)
__device__ int   g_idx[N_POS * 8];          // [pos][8], slots 0..5 used
__device__ float g_size_sum7[EMBED_D];      // sum_n size_w[n] / 7

// ---------------------------------------------------------------------------
// K0: fold the six 512-wide size_w rows and the /7 into one vector.
__global__ void size_sum_kernel(const float* __restrict__ size_w)
{
    const int d = threadIdx.x;              // 512 threads
    float s = 0.f;
    #pragma unroll
    for (int n = 0; n < 6; n++)
        s += size_w[n * EMBED_D + d];
    g_size_sum7[d] = s * INV_CONTRIB;
}

// ---------------------------------------------------------------------------
// K1: one thread per position; incremental hash over n = 3..8.
//     h_n = sum_{j=0}^{n-1} tok[s-j] * 260^j  (mod 2^23);  idx_n = h_n % 500000,
//     forced to 0 when s < n-1 (reference gathers shared_w[0] there).
__global__ __launch_bounds__(256)
void index_kernel(const int* __restrict__ tokens)
{
    const int pos = blockIdx.x * blockDim.x + threadIdx.x;
    if (pos >= N_POS) return;
    const int s  = pos & (SEQ_LEN - 1);
    const int* t = tokens + (pos - s);

    unsigned h = 0u, pw = 1u;
    int idx[8];
    // j = 0,1: build h_2 (prefix of all hashes)
    #pragma unroll
    for (int j = 0; j < 2; j++) {
        unsigned tk = (j <= s) ? (unsigned)t[s - j] : 0u;
        h  = (h + tk * pw) & HASH_MASK;
        pw = (pw * HASH_BASE) & HASH_MASK;
    }
    // n = 3..8: h_n = h_{n-1} + t[s-(n-1)] * 260^(n-1)
    #pragma unroll
    for (int n = 3; n <= 8; n++) {
        unsigned tk = ((n - 1) <= s) ? (unsigned)t[s - (n - 1)] : 0u;
        h  = (h + tk * pw) & HASH_MASK;
        pw = (pw * HASH_BASE) & HASH_MASK;
        idx[n - 3] = (s >= n - 1) ? (int)(h % N_BUCKETS) : 0;
    }
    idx[6] = 0; idx[7] = 0;

    int4* dst = reinterpret_cast<int4*>(&g_idx[pos * 8]);
    dst[0] = make_int4(idx[0], idx[1], idx[2], idx[3]);
    dst[1] = make_int4(idx[4], idx[5], idx[6], idx[7]);
}

// ---------------------------------------------------------------------------
// K2: pure gather. No smem, no barrier; 7 independent LDG.128 per thread.
__global__ __launch_bounds__(DV, 10)
void gather_kernel(const int*    __restrict__ tokens,
                   const float4* __restrict__ main_w,
                   const float4* __restrict__ shared_w,
                   float4*       __restrict__ out)
{
    const int pos = blockIdx.x;
    const int d   = (int)threadIdx.x;

    // Uniform (broadcast) loads: 2x int4 indices + 1 token. L1/L2 hits.
    const int4 i0 = *reinterpret_cast<const int4*>(&g_idx[pos * 8]);
    const int4 i1 = *reinterpret_cast<const int4*>(&g_idx[pos * 8 + 4]);
    const int tok = tokens[pos];

    // 7 independent row gathers (the DRAM traffic).
    float4 m  = __ldg(&main_w[(size_t)tok * DV + d]);
    float4 g0 = __ldg(&shared_w[(size_t)i0.x * DV + d]);
    float4 g1 = __ldg(&shared_w[(size_t)i0.y * DV + d]);
    float4 g2 = __ldg(&shared_w[(size_t)i0.z * DV + d]);
    float4 g3 = __ldg(&shared_w[(size_t)i0.w * DV + d]);
    float4 g4 = __ldg(&shared_w[(size_t)i1.x * DV + d]);
    float4 g5 = __ldg(&shared_w[(size_t)i1.y * DV + d]);

    const float4 zs = reinterpret_cast<const float4*>(g_size_sum7)[d];

    float4 acc;
    acc.x = m.x + g0.x + g1.x + g2.x + g3.x + g4.x + g5.x;
    acc.y = m.y + g0.y + g1.y + g2.y + g3.y + g4.y + g5.y;
    acc.z = m.z + g0.z + g1.z + g2.z + g3.z + g4.z + g5.z;
    acc.w = m.w + g0.w + g1.w + g2.w + g3.w + g4.w + g5.w;

    acc.x = fmaf(acc.x, INV_CONTRIB, zs.x);
    acc.y = fmaf(acc.y, INV_CONTRIB, zs.y);
    acc.z = fmaf(acc.z, INV_CONTRIB, zs.z);
    acc.w = fmaf(acc.w, INV_CONTRIB, zs.w);

    // Streaming store: keep the 64 MB output from evicting shared_w L2 lines.
    __stcs(&out[(size_t)pos * DV + d], acc);
}

// ---------------------------------------------------------------------------
extern "C" void kernel_launch(void* const* d_in, const int* in_sizes, int n_in,
                              void* d_out, int out_size)
{
    const int*    tokens   = (const int*)d_in[0];
    const float4* main_w   = (const float4*)d_in[1];
    const float4* shared_w = (const float4*)d_in[2];
    const float*  size_w   = (const float*)d_in[3];
    float4*       out      = (float4*)d_out;

    size_sum_kernel<<<1, EMBED_D>>>(size_w);
    index_kernel<<<(N_POS + 255) / 256, 256>>>(tokens);
    gather_kernel<<<N_POS, DV>>>(tokens, main_w, (const float4*)shared_w, out);
}

// round 5
// speedup vs baseline: 1.0313x; 1.0156x over previous
#include <cuda_runtime.h>
#include <cuda_bf16.h>

// HashNGramEmbedder — single fused kernel.
// out[b,s,:] = ( main_w[tok] + sum_{n=3..8} shared_w[idx_n] + sum_n size_w[n-3] ) / 7
// idx_n = ( sum_{j=0}^{n-1} tok[s-j] * 260^j mod 2^23 ) mod 500000, or 0 if s < n-1.
//
// Per-warp shfl prefix-scan computes all 6 hashes with no barrier / no smem:
//   lane j term_j = (t[s-j] * 260^j) & (2^23-1)      (j = lane & 7)
//   3-step inclusive scan over the 8-lane group -> P_k = sum_{j<=k} term_j (< 2^26)
//   lane k: idx = (s >= k) ? (P_k & MASK) % 500000 : 0   -> h_{k+1}'s bucket
//   gather n reads __shfl_sync(idx, n-1).
//
// Shapes (metadata order):
//   d_in[0] tokens   int32  [4, 8192]
//   d_in[1] main_w   f32    [259, 512]
//   d_in[2] shared_w f32    [500000, 512]
//   d_in[3] size_w   f32    [6, 512]
//   d_out            f32    [4, 8192, 512]

#define EMBED_D     512
#define DV          (EMBED_D / 4)      // 128 float4 lanes per row
#define SEQ_LEN     8192
#define N_BATCH     4
#define N_POS       (N_BATCH * SEQ_LEN)
#define HASH_MASK   ((1u << 23) - 1u)
#define N_BUCKETS   500000
#define INV_CONTRIB (1.0f / 7.0f)

// 260^j mod 2^23, j = 0..7
__constant__ unsigned c_pw[8] = {
    1u, 260u, 67600u, 798784u, 6357248u, 328704u, 1576960u, 7356416u
};

__global__ __launch_bounds__(DV, 10)
void hashngram_fused_kernel(const int*    __restrict__ tokens,
                            const float4* __restrict__ main_w,
                            const float4* __restrict__ shared_w,
                            const float4* __restrict__ size_w,
                            float4*       __restrict__ out)
{
    const int pos  = blockIdx.x;           // b * SEQ_LEN + s
    const int s    = pos & (SEQ_LEN - 1);
    const int* t   = tokens + (pos - s);   // batch-row base
    const int lane = (int)threadIdx.x & 31;
    const int k    = lane & 7;             // position within 8-lane hash group

    // ---- per-warp hash (every 8-lane group computes the same thing) ----
    const int tk = (k <= s) ? t[s - k] : 0;              // 8 consecutive ints, 1 sector
    unsigned v = ((unsigned)tk * c_pw[k]) & HASH_MASK;   // term_k

    unsigned u;
    u = __shfl_up_sync(0xffffffffu, v, 1, 8); if (k >= 1) v += u;
    u = __shfl_up_sync(0xffffffffu, v, 2, 8); if (k >= 2) v += u;
    u = __shfl_up_sync(0xffffffffu, v, 4, 8); if (k >= 4) v += u;
    // v on lane k = P_k = sum_{j<=k} term_j  (< 2^26)

    int idx = (s >= k) ? (int)((v & HASH_MASK) % N_BUCKETS) : 0;

    const int tok = __shfl_sync(0xffffffffu, tk, 0);     // t[s]
    const int i3  = __shfl_sync(0xffffffffu, idx, 2);    // n=3 .. n=8
    const int i4  = __shfl_sync(0xffffffffu, idx, 3);
    const int i5  = __shfl_sync(0xffffffffu, idx, 4);
    const int i6  = __shfl_sync(0xffffffffu, idx, 5);
    const int i7  = __shfl_sync(0xffffffffu, idx, 6);
    const int i8  = __shfl_sync(0xffffffffu, idx, 7);

    // ---- gathers: 7 independent LDG.128 (the DRAM traffic) ----
    const int d = (int)threadIdx.x;        // float4 lane within the 512-wide row
    float4 m  = __ldg(&main_w[(size_t)tok * DV + d]);
    float4 g0 = __ldg(&shared_w[(size_t)i3 * DV + d]);
    float4 g1 = __ldg(&shared_w[(size_t)i4 * DV + d]);
    float4 g2 = __ldg(&shared_w[(size_t)i5 * DV + d]);
    float4 g3 = __ldg(&shared_w[(size_t)i6 * DV + d]);
    float4 g4 = __ldg(&shared_w[(size_t)i7 * DV + d]);
    float4 g5 = __ldg(&shared_w[(size_t)i8 * DV + d]);

    float4 acc;
    acc.x = m.x + g0.x + g1.x + g2.x + g3.x + g4.x + g5.x;
    acc.y = m.y + g0.y + g1.y + g2.y + g3.y + g4.y + g5.y;
    acc.z = m.z + g0.z + g1.z + g2.z + g3.z + g4.z + g5.z;
    acc.w = m.w + g0.w + g1.w + g2.w + g3.w + g4.w + g5.w;

    // size_w: 12 KB, L2-resident; folded inline (no persistent registers).
    #pragma unroll
    for (int n = 0; n < 6; n++) {
        float4 z = __ldg(&size_w[n * DV + d]);
        acc.x += z.x; acc.y += z.y; acc.z += z.z; acc.w += z.w;
    }

    acc.x *= INV_CONTRIB;
    acc.y *= INV_CONTRIB;
    acc.z *= INV_CONTRIB;
    acc.w *= INV_CONTRIB;

    // Streaming store: keep the 64 MB output from evicting shared_w L2 lines.
    __stcs(&out[(size_t)pos * DV + d], acc);
}

extern "C" void kernel_launch(void* const* d_in, const int* in_sizes, int n_in,
                              void* d_out, int out_size)
{
    const int*    tokens   = (const int*)d_in[0];
    const float4* main_w   = (const float4*)d_in[1];
    const float4* shared_w = (const float4*)d_in[2];
    const float4* size_w   = (const float4*)d_in[3];
    float4*       out      = (float4*)d_out;

    hashngram_fused_kernel<<<N_POS, DV>>>(tokens, main_w, shared_w, size_w, out);
}